// round 1
// baseline (speedup 1.0000x reference)
#include <cuda_runtime.h>
#include <cstdint>
#include <cstddef>

// Problem constants (fixed by the reference setup_inputs)
#define BSZ   32
#define OUTD  8192
#define IND   8192
// LR / B
#define SCALE (0.01f / 32.0f)

// ---- packed f32x2 helpers (FFMA2 is only reachable via PTX fma.rn.f32x2) ----
__device__ __forceinline__ unsigned long long pack2(float lo, float hi) {
    unsigned long long r;
    asm("mov.b64 %0, {%1, %2};" : "=l"(r) : "f"(lo), "f"(hi));
    return r;
}
__device__ __forceinline__ void unpack2(unsigned long long v, float& lo, float& hi) {
    asm("mov.b64 {%0, %1}, %2;" : "=f"(lo), "=f"(hi) : "l"(v));
}
__device__ __forceinline__ void fma2(unsigned long long& d,
                                     unsigned long long a,
                                     unsigned long long b) {
    asm("fma.rn.f32x2 %0, %1, %2, %0;" : "+l"(d) : "l"(a), "l"(b));
}

// One CTA computes a 128(out) x 128(in) tile of the output.
// 256 threads, each owns an 8x8 register sub-tile accumulated as 8x4 f32x2.
__global__ __launch_bounds__(256) void hebb_update_kernel(
    const float* __restrict__ w,
    const float* __restrict__ pre,    // [BSZ, IND]
    const float* __restrict__ post,   // [BSZ, OUTD]
    float* __restrict__ out)
{
    __shared__ float pre_s[BSZ][128];
    __shared__ float post_s[BSZ][128];

    const int tid = threadIdx.x;
    const int i0 = blockIdx.x * 128;   // input-dim tile origin
    const int o0 = blockIdx.y * 128;   // output-dim tile origin

    // ---- cooperative tile load: 32x128 floats each = 1024 float4 per tile ----
    #pragma unroll
    for (int k = 0; k < 4; k++) {
        int idx = tid + k * 256;       // 0..1023
        int row = idx >> 5;            // 0..31  (batch index)
        int c4  = idx & 31;            // float4 column
        float4 pv = *(const float4*)(pre  + (size_t)row * IND  + i0 + c4 * 4);
        float4 qv = *(const float4*)(post + (size_t)row * OUTD + o0 + c4 * 4);
        *(float4*)(&pre_s[row][c4 * 4])  = pv;
        *(float4*)(&post_s[row][c4 * 4]) = qv;
    }
    __syncthreads();

    const int tx = tid & 15;           // input-dim lane  (16 x 8 = 128)
    const int ty = tid >> 4;           // output-dim lane (16 x 8 = 128)

    unsigned long long acc[8][4];
    #pragma unroll
    for (int r = 0; r < 8; r++)
        #pragma unroll
        for (int j = 0; j < 4; j++)
            acc[r][j] = 0ULL;          // (0.0f, 0.0f)

    // ---- K = 32 mainloop ----
    #pragma unroll 4
    for (int b = 0; b < BSZ; b++) {
        unsigned long long prp[4];
        #pragma unroll
        for (int j = 0; j < 4; j++)
            prp[j] = *(const unsigned long long*)(&pre_s[b][tx * 8 + j * 2]);

        unsigned long long pp[8];
        #pragma unroll
        for (int r = 0; r < 8; r++) {
            float p = post_s[b][ty * 8 + r];
            pp[r] = pack2(p, p);
        }

        #pragma unroll
        for (int r = 0; r < 8; r++)
            #pragma unroll
            for (int j = 0; j < 4; j++)
                fma2(acc[r][j], pp[r], prp[j]);
    }

    // ---- epilogue: out = clip(w + SCALE*acc, 0, 1), float4 in / float4 out ----
    const int orow = o0 + ty * 8;
    const int icol = i0 + tx * 8;

    #pragma unroll
    for (int r = 0; r < 8; r++) {
        const float* wrow = w   + (size_t)(orow + r) * IND + icol;
        float*       orow_p = out + (size_t)(orow + r) * IND + icol;
        #pragma unroll
        for (int q = 0; q < 2; q++) {
            float4 wv = *(const float4*)(wrow + q * 4);
            float a0, a1, a2, a3;
            unpack2(acc[r][2 * q + 0], a0, a1);
            unpack2(acc[r][2 * q + 1], a2, a3);
            float4 ov;
            ov.x = __saturatef(fmaf(a0, SCALE, wv.x));
            ov.y = __saturatef(fmaf(a1, SCALE, wv.y));
            ov.z = __saturatef(fmaf(a2, SCALE, wv.z));
            ov.w = __saturatef(fmaf(a3, SCALE, wv.w));
            *(float4*)(orow_p + q * 4) = ov;
        }
    }
}

extern "C" void kernel_launch(void* const* d_in, const int* in_sizes, int n_in,
                              void* d_out, int out_size)
{
    const float* w    = (const float*)d_in[0];   // weights      [8192, 8192]
    const float* pre  = (const float*)d_in[1];   // pre_activity [32, 8192]
    const float* post = (const float*)d_in[2];   // post_activity[32, 8192]
    float* out = (float*)d_out;                  // [8192, 8192] fp32

    dim3 grid(IND / 128, OUTD / 128);            // 64 x 64
    hebb_update_kernel<<<grid, 256>>>(w, pre, post, out);
}

// round 3
// speedup vs baseline: 1.9584x; 1.9584x over previous
#include <cuda_runtime.h>
#include <cuda_bf16.h>
#include <cstdint>
#include <cstddef>

#define OUTD 8192
#define IND  8192
#define BSZ  32
#define SCALE (0.01f / 32.0f)

// bf16 transposed operand buffers: [dim][batch], k-contiguous
__device__ __align__(16) __nv_bfloat16 g_preT[(size_t)IND * BSZ];   // [i][b]
__device__ __align__(16) __nv_bfloat16 g_postT[(size_t)OUTD * BSZ]; // [o][b]

__device__ __forceinline__ uint32_t smem_u32(const void* p) {
    uint32_t a;
    asm("{ .reg .u64 t; cvta.to.shared.u64 t, %1; cvt.u32.u64 %0, t; }" : "=r"(a) : "l"(p));
    return a;
}

__device__ __forceinline__ void ldmatrix_x4(uint32_t& r0, uint32_t& r1, uint32_t& r2,
                                            uint32_t& r3, uint32_t addr) {
    asm volatile("ldmatrix.sync.aligned.m8n8.x4.shared.b16 {%0,%1,%2,%3}, [%4];"
                 : "=r"(r0), "=r"(r1), "=r"(r2), "=r"(r3) : "r"(addr));
}

__device__ __forceinline__ void mma_bf16(float* d, uint32_t a0, uint32_t a1, uint32_t a2,
                                         uint32_t a3, uint32_t b0, uint32_t b1) {
    asm volatile(
        "mma.sync.aligned.m16n8k16.row.col.f32.bf16.bf16.f32 "
        "{%0,%1,%2,%3}, {%4,%5,%6,%7}, {%8,%9}, {%0,%1,%2,%3};"
        : "+f"(d[0]), "+f"(d[1]), "+f"(d[2]), "+f"(d[3])
        : "r"(a0), "r"(a1), "r"(a2), "r"(a3), "r"(b0), "r"(b1));
}

// ---------------- pre-pass: f32 [B, N] -> bf16 transposed [N, B] ----------------
__global__ __launch_bounds__(256) void convert_kernel(const float* __restrict__ pre,
                                                      const float* __restrict__ post) {
    int idx = blockIdx.x * 256 + threadIdx.x;  // 0..16383
    const float* src;
    __nv_bfloat16* dst;
    int col;
    if (idx < IND) { src = pre;  dst = g_preT;  col = idx; }
    else           { src = post; dst = g_postT; col = idx - IND; }

    float v[BSZ];
#pragma unroll
    for (int b = 0; b < BSZ; b++) v[b] = src[(size_t)b * IND + col];

    __nv_bfloat162 h[BSZ / 2];
#pragma unroll
    for (int j = 0; j < BSZ / 2; j++) h[j] = __floats2bfloat162_rn(v[2 * j], v[2 * j + 1]);

    uint4* d4 = reinterpret_cast<uint4*>(dst + (size_t)col * BSZ);
    const uint4* s4 = reinterpret_cast<const uint4*>(h);
#pragma unroll
    for (int q = 0; q < 4; q++) d4[q] = s4[q];
}

// ---------------- main kernel ----------------
// CTA tile: 128(o = m) x 128(i = n). 8 warps; warp w owns m-rows [w*16, w*16+16),
// all 128 n-cols. D = postT_tile @ preT_tile^T (row.col), K = 32 in 2 k16 steps.
// out = clip(w + SCALE*D, 0, 1).
#define SMS 80   // smem row stride in bytes (32 bf16 = 64B data + 16B pad, conflict-free)

__global__ __launch_bounds__(256, 2) void hebb_mma_kernel(
    const float* __restrict__ w, float* __restrict__ out)
{
    __shared__ __align__(16) uint8_t smA[128 * SMS];  // postT tile: [o][b]
    __shared__ __align__(16) uint8_t smB[128 * SMS];  // preT tile:  [i][b]

    const int tid = threadIdx.x;
    const int wid = tid >> 5;
    const int lane = tid & 31;
    const int i0 = blockIdx.x * 128;
    const int o0 = blockIdx.y * 128;

    // ---- load operand tiles (each 8KB contiguous in global) ----
    const uint4* Ag = reinterpret_cast<const uint4*>(g_postT + (size_t)o0 * BSZ);
    const uint4* Bg = reinterpret_cast<const uint4*>(g_preT  + (size_t)i0 * BSZ);
#pragma unroll
    for (int t = tid; t < 512; t += 256) {
        int row = t >> 2, c = t & 3;
        *reinterpret_cast<uint4*>(smA + row * SMS + c * 16) = Ag[t];
        *reinterpret_cast<uint4*>(smB + row * SMS + c * 16) = Bg[t];
    }
    __syncthreads();

    const uint32_t baseA = smem_u32(smA);
    const uint32_t baseB = smem_u32(smB);

    // ldmatrix lane->address mapping.
    // A (m16k16): matrices {rows0-7,k0-7},{rows8-15,k0-7},{rows0-7,k8-15},{rows8-15,k8-15}
    const int a_row = wid * 16 + ((lane >> 3) & 1) * 8 + (lane & 7);
    const uint32_t a_off = baseA + a_row * SMS + (lane >> 4) * 16;
    // B (2 n-frags per ldmatrix.x4): matrices {n0-7,k0-7},{n0-7,k8-15},{n8-15,k0-7},{n8-15,k8-15}
    const int b_row = ((lane >> 4) & 1) * 8 + (lane & 7);
    const uint32_t b_off = baseB + b_row * SMS + ((lane >> 3) & 1) * 16;

    float d[16][4];
#pragma unroll
    for (int f = 0; f < 16; f++)
#pragma unroll
        for (int q = 0; q < 4; q++) d[f][q] = 0.0f;

#pragma unroll
    for (int ks = 0; ks < 2; ks++) {             // k0 = ks*16 -> +32 bytes
        uint32_t a0, a1, a2, a3;
        ldmatrix_x4(a0, a1, a2, a3, a_off + ks * 32);
#pragma unroll
        for (int nf = 0; nf < 8; nf++) {         // 2 n-frags per iteration
            uint32_t b0, b1, b2, b3;
            ldmatrix_x4(b0, b1, b2, b3, b_off + nf * 16 * SMS + ks * 32);
            mma_bf16(d[2 * nf],     a0, a1, a2, a3, b0, b1);
            mma_bf16(d[2 * nf + 1], a0, a1, a2, a3, b2, b3);
        }
    }

    // ---- epilogue: fragment -> global, float2 accesses (full 32B sectors) ----
    const int g  = lane >> 2;
    const int tq = lane & 3;
    const int row0 = o0 + wid * 16 + g;
    const int col0 = i0 + tq * 2;

#pragma unroll
    for (int f = 0; f < 16; f++) {
#pragma unroll
        for (int h = 0; h < 2; h++) {
            const size_t off = (size_t)(row0 + h * 8) * IND + col0 + f * 8;
            float2 wv = *reinterpret_cast<const float2*>(w + off);
            float2 ov;
            ov.x = __saturatef(fmaf(d[f][2 * h + 0], SCALE, wv.x));
            ov.y = __saturatef(fmaf(d[f][2 * h + 1], SCALE, wv.y));
            *reinterpret_cast<float2*>(out + off) = ov;
        }
    }
}

extern "C" void kernel_launch(void* const* d_in, const int* in_sizes, int n_in,
                              void* d_out, int out_size)
{
    const float* w    = (const float*)d_in[0];  // weights       [8192, 8192]
    const float* pre  = (const float*)d_in[1];  // pre_activity  [32, 8192]
    const float* post = (const float*)d_in[2];  // post_activity [32, 8192]
    float* out = (float*)d_out;                 // [8192, 8192] fp32

    convert_kernel<<<(IND + OUTD) / 256, 256>>>(pre, post);
    dim3 grid(IND / 128, OUTD / 128);           // 64 x 64
    hebb_mma_kernel<<<grid, 256>>>(w, out);
}

// round 4
// speedup vs baseline: 2.1435x; 1.0945x over previous
#include <cuda_runtime.h>
#include <cuda_bf16.h>
#include <cstdint>
#include <cstddef>

#define OUTD 8192
#define IND  8192
#define BSZ  32
#define SCALE (0.01f / 32.0f)

// bf16 transposed operand buffers: [dim][batch], k-contiguous
__device__ __align__(16) __nv_bfloat16 g_preT[(size_t)IND * BSZ];   // [i][b]
__device__ __align__(16) __nv_bfloat16 g_postT[(size_t)OUTD * BSZ]; // [o][b]

__device__ __forceinline__ uint32_t smem_u32(const void* p) {
    uint32_t a;
    asm("{ .reg .u64 t; cvta.to.shared.u64 t, %1; cvt.u32.u64 %0, t; }" : "=r"(a) : "l"(p));
    return a;
}

__device__ __forceinline__ void ldmatrix_x4(uint32_t& r0, uint32_t& r1, uint32_t& r2,
                                            uint32_t& r3, uint32_t addr) {
    asm volatile("ldmatrix.sync.aligned.m8n8.x4.shared.b16 {%0,%1,%2,%3}, [%4];"
                 : "=r"(r0), "=r"(r1), "=r"(r2), "=r"(r3) : "r"(addr));
}

__device__ __forceinline__ void mma_bf16(float* d, uint32_t a0, uint32_t a1, uint32_t a2,
                                         uint32_t a3, uint32_t b0, uint32_t b1) {
    asm volatile(
        "mma.sync.aligned.m16n8k16.row.col.f32.bf16.bf16.f32 "
        "{%0,%1,%2,%3}, {%4,%5,%6,%7}, {%8,%9}, {%0,%1,%2,%3};"
        : "+f"(d[0]), "+f"(d[1]), "+f"(d[2]), "+f"(d[3])
        : "r"(a0), "r"(a1), "r"(a2), "r"(a3), "r"(b0), "r"(b1));
}

// ---------------- pre-pass: f32 [B, N] -> bf16 transposed [N, B] ----------------
// 65536 threads: thread = (bg, col). bg = batch-group of 8. Loads coalesced across cols.
__global__ __launch_bounds__(256) void convert_kernel(const float* __restrict__ pre,
                                                      const float* __restrict__ post) {
    int idx = blockIdx.x * 256 + threadIdx.x;   // 0..65535
    int col = idx & 16383;                      // 0..16383
    int bg  = idx >> 14;                        // 0..3 (batches bg*8 .. bg*8+7)

    const float* src;
    __nv_bfloat16* dst;
    int c;
    if (col < IND) { src = pre;  dst = g_preT;  c = col; }
    else           { src = post; dst = g_postT; c = col - IND; }

    float v[8];
#pragma unroll
    for (int b = 0; b < 8; b++) v[b] = src[(size_t)(bg * 8 + b) * IND + c];

    __nv_bfloat162 h[4];
#pragma unroll
    for (int j = 0; j < 4; j++) h[j] = __floats2bfloat162_rn(v[2 * j], v[2 * j + 1]);

    *reinterpret_cast<uint4*>(dst + (size_t)c * BSZ + bg * 8) =
        *reinterpret_cast<const uint4*>(h);
}

// ---------------- main kernel ----------------
// CTA tile: 128(o = m) x 128(i = n). 8 warps; warp w owns m-rows [w*16, w*16+16).
// D = postT_tile @ preT_tile^T (row.col), K = 32 in 2 k16 steps.
// out = clip(w + SCALE*D, 0, 1).
#define SMS 80   // smem row stride in bytes (32 bf16 = 64B data + 16B pad)

__global__ __launch_bounds__(256, 2) void hebb_mma_kernel(
    const float* __restrict__ w, float* __restrict__ out)
{
    __shared__ __align__(16) uint8_t smA[128 * SMS];  // postT tile: [o][b]
    __shared__ __align__(16) uint8_t smB[128 * SMS];  // preT tile:  [i][b]

    const int tid = threadIdx.x;
    const int wid = tid >> 5;
    const int lane = tid & 31;
    const int i0 = blockIdx.x * 128;
    const int o0 = blockIdx.y * 128;

    // ---- load operand tiles (each 8KB contiguous in global) ----
    const uint4* Ag = reinterpret_cast<const uint4*>(g_postT + (size_t)o0 * BSZ);
    const uint4* Bg = reinterpret_cast<const uint4*>(g_preT  + (size_t)i0 * BSZ);
#pragma unroll
    for (int t = tid; t < 512; t += 256) {
        int row = t >> 2, c = t & 3;
        *reinterpret_cast<uint4*>(smA + row * SMS + c * 16) = Ag[t];
        *reinterpret_cast<uint4*>(smB + row * SMS + c * 16) = Bg[t];
    }
    __syncthreads();

    const uint32_t baseA = smem_u32(smA);
    const uint32_t baseB = smem_u32(smB);

    // A (m16k16): matrices {rows0-7,k0-7},{rows8-15,k0-7},{rows0-7,k8-15},{rows8-15,k8-15}
    const int a_row = wid * 16 + ((lane >> 3) & 1) * 8 + (lane & 7);
    const uint32_t a_off = baseA + a_row * SMS + (lane >> 4) * 16;
    // B: matrices {n0-7,k0-7},{n0-7,k8-15},{n8-15,k0-7},{n8-15,k8-15}
    const int b_row = ((lane >> 4) & 1) * 8 + (lane & 7);
    const uint32_t b_off = baseB + b_row * SMS + ((lane >> 3) & 1) * 16;

    float d[16][4];
#pragma unroll
    for (int f = 0; f < 16; f++)
#pragma unroll
        for (int q = 0; q < 4; q++) d[f][q] = 0.0f;

#pragma unroll
    for (int ks = 0; ks < 2; ks++) {
        uint32_t a0, a1, a2, a3;
        ldmatrix_x4(a0, a1, a2, a3, a_off + ks * 32);
#pragma unroll
        for (int nf = 0; nf < 8; nf++) {
            uint32_t b0, b1, b2, b3;
            ldmatrix_x4(b0, b1, b2, b3, b_off + nf * 16 * SMS + ks * 32);
            mma_bf16(d[2 * nf],     a0, a1, a2, a3, b0, b1);
            mma_bf16(d[2 * nf + 1], a0, a1, a2, a3, b2, b3);
        }
    }

    // ---- epilogue: pair-shuffle fragments into float4, 128-bit global R/W ----
    // Lane = g*4 + tq. Lane pair (tq even/odd) exchange float2s so each thread
    // holds 4 consecutive columns of one fragment of the pair.
    const int g  = lane >> 2;
    const int tq = lane & 3;
    const int j  = tq >> 1;
    const int s  = tq & 1;
    const int row_base = o0 + wid * 16 + g;

#pragma unroll
    for (int u = 0; u < 8; u++) {
        const int f0 = 2 * u, f1 = 2 * u + 1;
        const int myf = s ? f1 : f0;
        const size_t colbase = (size_t)(i0 + myf * 8 + j * 4);
#pragma unroll
        for (int h = 0; h < 2; h++) {
            float2 give;
            give.x = s ? d[f0][2 * h]     : d[f1][2 * h];
            give.y = s ? d[f0][2 * h + 1] : d[f1][2 * h + 1];
            unsigned long long gv = *reinterpret_cast<unsigned long long*>(&give);
            unsigned long long rv = __shfl_xor_sync(0xFFFFFFFFu, gv, 1);
            float2 recv = *reinterpret_cast<float2*>(&rv);

            float4 acc4;
            if (s == 0) {
                acc4.x = d[f0][2 * h]; acc4.y = d[f0][2 * h + 1];
                acc4.z = recv.x;       acc4.w = recv.y;
            } else {
                acc4.x = recv.x;       acc4.y = recv.y;
                acc4.z = d[f1][2 * h]; acc4.w = d[f1][2 * h + 1];
            }

            const size_t off = (size_t)(row_base + h * 8) * IND + colbase;
            float4 wv = *reinterpret_cast<const float4*>(w + off);
            float4 ov;
            ov.x = __saturatef(fmaf(acc4.x, SCALE, wv.x));
            ov.y = __saturatef(fmaf(acc4.y, SCALE, wv.y));
            ov.z = __saturatef(fmaf(acc4.z, SCALE, wv.z));
            ov.w = __saturatef(fmaf(acc4.w, SCALE, wv.w));
            *reinterpret_cast<float4*>(out + off) = ov;
        }
    }
}

extern "C" void kernel_launch(void* const* d_in, const int* in_sizes, int n_in,
                              void* d_out, int out_size)
{
    const float* w    = (const float*)d_in[0];  // weights       [8192, 8192]
    const float* pre  = (const float*)d_in[1];  // pre_activity  [32, 8192]
    const float* post = (const float*)d_in[2];  // post_activity [32, 8192]
    float* out = (float*)d_out;                 // [8192, 8192] fp32

    convert_kernel<<<256, 256>>>(pre, post);
    dim3 grid(IND / 128, OUTD / 128);           // 64 x 64
    hebb_mma_kernel<<<grid, 256>>>(w, out);
}

// round 5
// speedup vs baseline: 2.1547x; 1.0052x over previous
#include <cuda_runtime.h>
#include <cuda_bf16.h>
#include <cstdint>
#include <cstddef>

#define OUTD 8192
#define IND  8192
#define BSZ  32
#define SCALE (0.01f / 32.0f)

// bf16 transposed operand buffers: [dim][batch], k-contiguous
__device__ __align__(16) __nv_bfloat16 g_preT[(size_t)IND * BSZ];   // [i][b]
__device__ __align__(16) __nv_bfloat16 g_postT[(size_t)OUTD * BSZ]; // [o][b]

__device__ __forceinline__ uint32_t smem_u32(const void* p) {
    uint32_t a;
    asm("{ .reg .u64 t; cvta.to.shared.u64 t, %1; cvt.u32.u64 %0, t; }" : "=r"(a) : "l"(p));
    return a;
}

__device__ __forceinline__ void ldmatrix_x4(uint32_t& r0, uint32_t& r1, uint32_t& r2,
                                            uint32_t& r3, uint32_t addr) {
    asm volatile("ldmatrix.sync.aligned.m8n8.x4.shared.b16 {%0,%1,%2,%3}, [%4];"
                 : "=r"(r0), "=r"(r1), "=r"(r2), "=r"(r3) : "r"(addr));
}

__device__ __forceinline__ void mma_bf16(float* d, uint32_t a0, uint32_t a1, uint32_t a2,
                                         uint32_t a3, uint32_t b0, uint32_t b1) {
    asm volatile(
        "mma.sync.aligned.m16n8k16.row.col.f32.bf16.bf16.f32 "
        "{%0,%1,%2,%3}, {%4,%5,%6,%7}, {%8,%9}, {%0,%1,%2,%3};"
        : "+f"(d[0]), "+f"(d[1]), "+f"(d[2]), "+f"(d[3])
        : "r"(a0), "r"(a1), "r"(a2), "r"(a3), "r"(b0), "r"(b1));
}

// ---------------- pre-pass: f32 [B, N] -> bf16 transposed [N, B] ----------------
__global__ __launch_bounds__(256) void convert_kernel(const float* __restrict__ pre,
                                                      const float* __restrict__ post) {
    int idx = blockIdx.x * 256 + threadIdx.x;   // 0..65535
    int col = idx & 16383;                      // 0..16383
    int bg  = idx >> 14;                        // 0..3 (batches bg*8 .. bg*8+7)

    const float* src;
    __nv_bfloat16* dst;
    int c;
    if (col < IND) { src = pre;  dst = g_preT;  c = col; }
    else           { src = post; dst = g_postT; c = col - IND; }

    float v[8];
#pragma unroll
    for (int b = 0; b < 8; b++) v[b] = src[(size_t)(bg * 8 + b) * IND + c];

    __nv_bfloat162 h[4];
#pragma unroll
    for (int j = 0; j < 4; j++) h[j] = __floats2bfloat162_rn(v[2 * j], v[2 * j + 1]);

    *reinterpret_cast<uint4*>(dst + (size_t)c * BSZ + bg * 8) =
        *reinterpret_cast<const uint4*>(h);
}

// ---------------- main kernel ----------------
// CTA tile: 128(o = m) x 64(i = n). 8 warps; warp w owns m-rows [w*16, w*16+16),
// n = 64. D = postT_tile @ preT_tile^T (row.col), K = 32 in 2 k16 steps.
// out = clip(w + SCALE*D, 0, 1). 3 CTAs/SM for latency hiding.
#define SMS 80   // smem row stride in bytes (32 bf16 = 64B data + 16B pad)

__global__ __launch_bounds__(256, 3) void hebb_mma_kernel(
    const float* __restrict__ w, float* __restrict__ out)
{
    __shared__ __align__(16) uint8_t smA[128 * SMS];  // postT tile: [o][b]
    __shared__ __align__(16) uint8_t smB[64 * SMS];   // preT tile:  [i][b]

    const int tid = threadIdx.x;
    const int wid = tid >> 5;
    const int lane = tid & 31;
    const int i0 = blockIdx.x * 64;
    const int o0 = blockIdx.y * 128;

    // ---- load operand tiles (contiguous in global: A 8KB, B 4KB) ----
    const uint4* Ag = reinterpret_cast<const uint4*>(g_postT + (size_t)o0 * BSZ);
    const uint4* Bg = reinterpret_cast<const uint4*>(g_preT  + (size_t)i0 * BSZ);
#pragma unroll
    for (int t = tid; t < 512; t += 256) {
        int row = t >> 2, c = t & 3;
        *reinterpret_cast<uint4*>(smA + row * SMS + c * 16) = Ag[t];
    }
    {
        int row = tid >> 2, c = tid & 3;   // 256 threads cover 64 rows x 4 segs
        *reinterpret_cast<uint4*>(smB + row * SMS + c * 16) = Bg[tid];
    }
    __syncthreads();

    const uint32_t baseA = smem_u32(smA);
    const uint32_t baseB = smem_u32(smB);

    // A (m16k16): matrices {rows0-7,k0-7},{rows8-15,k0-7},{rows0-7,k8-15},{rows8-15,k8-15}
    const int a_row = wid * 16 + ((lane >> 3) & 1) * 8 + (lane & 7);
    const uint32_t a_off = baseA + a_row * SMS + (lane >> 4) * 16;
    // B: matrices {n0-7,k0-7},{n0-7,k8-15},{n8-15,k0-7},{n8-15,k8-15}
    const int b_row = ((lane >> 4) & 1) * 8 + (lane & 7);
    const uint32_t b_off = baseB + b_row * SMS + ((lane >> 3) & 1) * 16;

    float d[8][4];
#pragma unroll
    for (int f = 0; f < 8; f++)
#pragma unroll
        for (int q = 0; q < 4; q++) d[f][q] = 0.0f;

#pragma unroll
    for (int ks = 0; ks < 2; ks++) {
        uint32_t a0, a1, a2, a3;
        ldmatrix_x4(a0, a1, a2, a3, a_off + ks * 32);
#pragma unroll
        for (int nf = 0; nf < 4; nf++) {
            uint32_t b0, b1, b2, b3;
            ldmatrix_x4(b0, b1, b2, b3, b_off + nf * 16 * SMS + ks * 32);
            mma_bf16(d[2 * nf],     a0, a1, a2, a3, b0, b1);
            mma_bf16(d[2 * nf + 1], a0, a1, a2, a3, b2, b3);
        }
    }

    // ---- epilogue: pair-shuffle fragments into float4, 128-bit global R/W ----
    const int g  = lane >> 2;
    const int tq = lane & 3;
    const int j  = tq >> 1;
    const int s  = tq & 1;
    const int row_base = o0 + wid * 16 + g;

#pragma unroll
    for (int u = 0; u < 4; u++) {
        const int f0 = 2 * u, f1 = 2 * u + 1;
        const int myf = s ? f1 : f0;
        const size_t colbase = (size_t)(i0 + myf * 8 + j * 4);
#pragma unroll
        for (int h = 0; h < 2; h++) {
            float2 give;
            give.x = s ? d[f0][2 * h]     : d[f1][2 * h];
            give.y = s ? d[f0][2 * h + 1] : d[f1][2 * h + 1];
            unsigned long long gv = *reinterpret_cast<unsigned long long*>(&give);
            unsigned long long rv = __shfl_xor_sync(0xFFFFFFFFu, gv, 1);
            float2 recv = *reinterpret_cast<float2*>(&rv);

            float4 acc4;
            if (s == 0) {
                acc4.x = d[f0][2 * h]; acc4.y = d[f0][2 * h + 1];
                acc4.z = recv.x;       acc4.w = recv.y;
            } else {
                acc4.x = recv.x;       acc4.y = recv.y;
                acc4.z = d[f1][2 * h]; acc4.w = d[f1][2 * h + 1];
            }

            const size_t off = (size_t)(row_base + h * 8) * IND + colbase;
            float4 wv = *reinterpret_cast<const float4*>(w + off);
            float4 ov;
            ov.x = __saturatef(fmaf(acc4.x, SCALE, wv.x));
            ov.y = __saturatef(fmaf(acc4.y, SCALE, wv.y));
            ov.z = __saturatef(fmaf(acc4.z, SCALE, wv.z));
            ov.w = __saturatef(fmaf(acc4.w, SCALE, wv.w));
            *reinterpret_cast<float4*>(out + off) = ov;
        }
    }
}

extern "C" void kernel_launch(void* const* d_in, const int* in_sizes, int n_in,
                              void* d_out, int out_size)
{
    const float* w    = (const float*)d_in[0];  // weights       [8192, 8192]
    const float* pre  = (const float*)d_in[1];  // pre_activity  [32, 8192]
    const float* post = (const float*)d_in[2];  // post_activity [32, 8192]
    float* out = (float*)d_out;                 // [8192, 8192] fp32

    convert_kernel<<<256, 256>>>(pre, post);
    dim3 grid(IND / 64, OUTD / 128);            // 128 x 64 = 8192 CTAs
    hebb_mma_kernel<<<grid, 256>>>(w, out);
}